// round 3
// baseline (speedup 1.0000x reference)
#include <cuda_runtime.h>

#define RESO    128
#define NRAYS   16384
#define NSAMP   192
#define STEP    0.5f
#define NVOX    (RESO*RESO*RESO)

// Padded grid: per voxel 32 floats = 8 float4 = 128B (one cache line).
// slots [0..26] = SH channels, [27] = density, [28..31] = 0 padding.
__device__ float4 g_grid[NVOX * 8];

// ---------------------------------------------------------------------------
// Pass 0: repack (density, sh) -> padded 128B-per-voxel layout
// ---------------------------------------------------------------------------
__global__ void __launch_bounds__(256)
repack_kernel(const float* __restrict__ density, const float* __restrict__ sh)
{
    int v = blockIdx.x * 256 + threadIdx.x;
    if (v >= NVOX) return;
    const float* s = sh + (size_t)v * 27;
    float vals[32];
#pragma unroll
    for (int i = 0; i < 27; i++) vals[i] = s[i];
    vals[27] = density[v];
    vals[28] = vals[29] = vals[30] = vals[31] = 0.f;
    float4* dst = g_grid + v * 8;
#pragma unroll
    for (int i = 0; i < 8; i++)
        dst[i] = make_float4(vals[4*i], vals[4*i+1], vals[4*i+2], vals[4*i+3]);
}

// ---------------------------------------------------------------------------
// Pass 1: render. One warp per ray. 4 samples in flight per iteration,
// 8 lanes cooperate on one sample (lane = float4 slot of the 128B voxel line).
// ---------------------------------------------------------------------------
__global__ void __launch_bounds__(256)
render_kernel(const float* __restrict__ origins,
              const float* __restrict__ dirs,
              float* __restrict__ out)
{
    const unsigned FULL = 0xFFFFFFFFu;
    int gw   = (blockIdx.x * blockDim.x + threadIdx.x) >> 5;   // ray id
    int lane = threadIdx.x & 31;
    if (gw >= NRAYS) return;
    int grp = lane >> 3;     // sample-in-flight id (0..3)
    int sub = lane & 7;      // float4 slot within voxel line (0..7)

    float ox = origins[gw*3+0], oy = origins[gw*3+1], oz = origins[gw*3+2];
    float dx = dirs[gw*3+0],    dy = dirs[gw*3+1],    dz = dirs[gw*3+2];

    // Real SH degree-2 basis (svox2 convention)
    float basis[9];
    basis[0] =  0.28209479177387814f;
    basis[1] = -0.4886025119029199f * dy;
    basis[2] =  0.4886025119029199f * dz;
    basis[3] = -0.4886025119029199f * dx;
    basis[4] =  1.0925484305920792f * dx * dy;
    basis[5] = -1.0925484305920792f * dy * dz;
    basis[6] =  0.31539156525252005f * (2.f*dz*dz - dx*dx - dy*dy);
    basis[7] = -1.0925484305920792f * dx * dz;
    basis[8] =  0.5462742152960396f * (dx*dx - dy*dy);

    // Per-lane channel->color routing, premultiplied with basis. Lane `sub`
    // owns channels [4*sub .. 4*sub+3]. ch in [0,9)=R, [9,18)=G, [18,27)=B,
    // 27=density, >=28 padding.
    float brr[4], bgg[4], bbb[4];
#pragma unroll
    for (int m = 0; m < 4; m++) {
        int ch = 4*sub + m;
        float bk = (ch < 27) ? basis[ch % 9] : 0.f;
        brr[m] = (ch < 9)              ? bk : 0.f;
        bgg[m] = (ch >= 9 && ch < 18)  ? bk : 0.f;
        bbb[m] = (ch >= 18 && ch < 27) ? bk : 0.f;
    }

    const float4* __restrict__ grid = g_grid;

    float T = 1.f;
    float cr = 0.f, cg = 0.f, cb = 0.f;

    for (int it = 0; it < NSAMP/4; ++it) {
        int   s = it*4 + grp;
        float t = ((float)s + 0.5f) * STEP;
        float px = fmaf(t, dx, ox);
        float py = fmaf(t, dy, oy);
        float pz = fmaf(t, dz, oz);
        bool inb = (px >= 0.f) && (px <= 127.f) &&
                   (py >= 0.f) && (py <= 127.f) &&
                   (pz >= 0.f) && (pz <= 127.f);
        // Samples in-bounds form a prefix of the ray (convex box). If all 4
        // current samples are out, every later one is too: exact early exit.
        if (__ballot_sync(FULL, inb) == 0u) break;

        float fx = floorf(px), fy = floorf(py), fz = floorf(pz);
        float rx = px - fx,    ry = py - fy,    rz = pz - fz;   // frac = p - floor(p) (ref semantics)
        int ix = min(max((int)fx, 0), RESO - 2);
        int iy = min(max((int)fy, 0), RESO - 2);
        int iz = min(max((int)fz, 0), RESO - 2);
        float wx0 = 1.f - rx, wy0 = 1.f - ry, wz0 = 1.f - rz;

        float4 a = make_float4(0.f, 0.f, 0.f, 0.f);
        if (inb) {
            int base = (((ix << 7) | iy) << 7 | iz) * 8 + sub;
            const float4* p = grid + base;
#pragma unroll
            for (int c = 0; c < 8; ++c) {
                float w = ((c & 4) ? rx : wx0) *
                          ((c & 2) ? ry : wy0) *
                          ((c & 1) ? rz : wz0);
                float4 v = __ldg(p + ((c & 4) ? (RESO*RESO*8) : 0)
                                   + ((c & 2) ? (RESO*8)      : 0)
                                   + ((c & 1) ? 8             : 0));
                a.x = fmaf(w, v.x, a.x);
                a.y = fmaf(w, v.y, a.y);
                a.z = fmaf(w, v.z, a.z);
                a.w = fmaf(w, v.w, a.w);
            }
        }

        // Per-lane partial dot products against the routed basis
        float pr = a.x*brr[0] + a.y*brr[1] + a.z*brr[2] + a.w*brr[3];
        float pg = a.x*bgg[0] + a.y*bgg[1] + a.z*bgg[2] + a.w*bgg[3];
        float pb = a.x*bbb[0] + a.y*bbb[1] + a.z*bbb[2] + a.w*bbb[3];
        float ps = (sub == 6) ? a.w : 0.f;   // channel 27 (density) lives in lane 6's .w

        // Reduce within each aligned 8-lane group (all lanes end with group sum)
#pragma unroll
        for (int off = 1; off <= 4; off <<= 1) {
            pr += __shfl_xor_sync(FULL, pr, off);
            pg += __shfl_xor_sync(FULL, pg, off);
            pb += __shfl_xor_sync(FULL, pb, off);
            ps += __shfl_xor_sync(FULL, ps, off);
        }

        float sigma = (inb && ps > 1e-10f) ? ps : 0.f;
        float la    = -sigma * STEP;                 // log per-step transmittance
        float alpha = 1.f - expf(la);
        float r = fmaxf(pr + 0.5f, 0.f);
        float g = fmaxf(pg + 0.5f, 0.f);
        float b = fmaxf(pb + 0.5f, 0.f);

        // Sequential transmittance across the 4 in-flight samples
        float la0 = __shfl_sync(FULL, la, 0);
        float la1 = __shfl_sync(FULL, la, 8);
        float la2 = __shfl_sync(FULL, la, 16);
        float la3 = __shfl_sync(FULL, la, 24);
        float pre = 0.f;
        if (grp > 0) pre += la0;
        if (grp > 1) pre += la1;
        if (grp > 2) pre += la2;
        float w = T * expf(pre) * alpha;
        cr = fmaf(w, r, cr);
        cg = fmaf(w, g, cg);
        cb = fmaf(w, b, cb);
        T *= expf(la0 + la1 + la2 + la3);

        // Remaining contribution bounded by T * O(rgb): <=1e-7 abs error. Safe.
        if (T < 1e-8f) break;
    }

    // Sum per-group color accumulators across the 4 groups
    cr += __shfl_xor_sync(FULL, cr, 8);  cr += __shfl_xor_sync(FULL, cr, 16);
    cg += __shfl_xor_sync(FULL, cg, 8);  cg += __shfl_xor_sync(FULL, cg, 16);
    cb += __shfl_xor_sync(FULL, cb, 8);  cb += __shfl_xor_sync(FULL, cb, 16);

    if (lane == 0) {
        out[gw*3+0] = cr + T;   // + T_final * EMPTY_BRIGHT (=1)
        out[gw*3+1] = cg + T;
        out[gw*3+2] = cb + T;
    }
}

// ---------------------------------------------------------------------------
extern "C" void kernel_launch(void* const* d_in, const int* in_sizes, int n_in,
                              void* d_out, int out_size)
{
    const float* origins = (const float*)d_in[0];   // [NRAYS,3]
    const float* dirs    = (const float*)d_in[1];   // [NRAYS,3]
    const float* density = (const float*)d_in[2];   // [128^3]
    const float* sh      = (const float*)d_in[3];   // [128^3,27]
    float* out = (float*)d_out;                     // [NRAYS,3]

    repack_kernel<<<(NVOX + 255) / 256, 256>>>(density, sh);
    render_kernel<<<(NRAYS * 32) / 256, 256>>>(origins, dirs, out);
}

// round 5
// speedup vs baseline: 1.4392x; 1.4392x over previous
#include <cuda_runtime.h>
#include <cuda_fp16.h>

#define RESO    128
#define NRAYS   16384
#define NSAMP   192
#define STEP    0.5f
#define NVOX    (RESO*RESO*RESO)

// Padded fp16 grid: 32 halves = 64B per voxel (2 voxels per 128B line).
// slots [0..26] = SH channels, [27] = density, [28..31] never read (lane 7 skips).
__device__ __half g_half[NVOX * 32];

// ---------------------------------------------------------------------------
// Pass 0a: repack sh -> fp16 padded layout. Fully coalesced float4 reads.
// ---------------------------------------------------------------------------
__global__ void __launch_bounds__(256)
repack_sh(const float* __restrict__ sh)
{
    int idx = (blockIdx.x * 256 + threadIdx.x) * 4;     // flat index into sh
    if (idx >= NVOX * 27) return;
    float4 f = *(const float4*)(sh + idx);
    int v = idx / 27;
    int c = idx - v * 27;
    float vals[4] = {f.x, f.y, f.z, f.w};
#pragma unroll
    for (int j = 0; j < 4; j++) {
        g_half[v * 32 + c] = __float2half(vals[j]);
        if (++c == 27) { c = 0; ++v; }
    }
}

// Pass 0b: density -> slot 27
__global__ void __launch_bounds__(256)
repack_density(const float* __restrict__ density)
{
    int v = blockIdx.x * 256 + threadIdx.x;
    if (v >= NVOX) return;
    g_half[v * 32 + 27] = __float2half(density[v]);
}

// ---------------------------------------------------------------------------
// Pass 1: render. One warp per ray; 4 samples in flight (8 lanes/sample);
// lane sub owns channels [4*sub..4*sub+3] as 4 halves (LDG.64). Lane 7 idle
// on loads (its channels are zero padding).
// ---------------------------------------------------------------------------
__global__ void __launch_bounds__(128)
render_kernel(const float* __restrict__ origins,
              const float* __restrict__ dirs,
              float* __restrict__ out)
{
    const unsigned FULL = 0xFFFFFFFFu;
    int gw   = (blockIdx.x * blockDim.x + threadIdx.x) >> 5;   // ray id
    int lane = threadIdx.x & 31;
    if (gw >= NRAYS) return;
    int grp = lane >> 3;       // sample-in-flight (0..3)
    int sub = lane & 7;        // channel-quad slot (0..7)
    bool oddl = sub & 1;

    float ox = origins[gw*3+0], oy = origins[gw*3+1], oz = origins[gw*3+2];
    float dx = dirs[gw*3+0],    dy = dirs[gw*3+1],    dz = dirs[gw*3+2];

    // Real SH degree-2 basis (svox2 convention)
    float basis[9];
    basis[0] =  0.28209479177387814f;
    basis[1] = -0.4886025119029199f * dy;
    basis[2] =  0.4886025119029199f * dz;
    basis[3] = -0.4886025119029199f * dx;
    basis[4] =  1.0925484305920792f * dx * dy;
    basis[5] = -1.0925484305920792f * dy * dz;
    basis[6] =  0.31539156525252005f * (2.f*dz*dz - dx*dx - dy*dy);
    basis[7] = -1.0925484305920792f * dx * dz;
    basis[8] =  0.5462742152960396f * (dx*dx - dy*dy);

    // Per-lane channel->color routing premultiplied with basis.
    float brr[4], bgg[4], bbb[4];
#pragma unroll
    for (int m = 0; m < 4; m++) {
        int ch = 4*sub + m;
        float bk = (ch < 27) ? basis[ch % 9] : 0.f;
        brr[m] = (ch < 9)              ? bk : 0.f;
        bgg[m] = (ch >= 9 && ch < 18)  ? bk : 0.f;
        bbb[m] = (ch >= 18 && ch < 27) ? bk : 0.f;
    }

    const uint2* __restrict__ gh = (const uint2*)g_half;   // 4 halves per uint2

    float T = 1.f;
    float cr = 0.f, cg = 0.f, cb = 0.f;

    for (int it = 0; it < NSAMP/4; ++it) {
        int   s = it*4 + grp;
        float t = ((float)s + 0.5f) * STEP;
        float px = fmaf(t, dx, ox);
        float py = fmaf(t, dy, oy);
        float pz = fmaf(t, dz, oz);
        bool inb = (px >= 0.f) && (px <= 127.f) &&
                   (py >= 0.f) && (py <= 127.f) &&
                   (pz >= 0.f) && (pz <= 127.f);
        // In-bounds samples form a prefix (convex box): exact early exit.
        if (__ballot_sync(FULL, inb) == 0u) break;

        float fx = floorf(px), fy = floorf(py), fz = floorf(pz);
        float rx = px - fx,    ry = py - fy,    rz = pz - fz;
        int ix = min(max((int)fx, 0), RESO - 2);
        int iy = min(max((int)fy, 0), RESO - 2);
        int iz = min(max((int)fz, 0), RESO - 2);
        float wx0 = 1.f - rx, wy0 = 1.f - ry, wz0 = 1.f - rz;

        float a0 = 0.f, a1 = 0.f, a2 = 0.f, a3 = 0.f;
        if (inb && sub != 7) {
            // uint2 units: voxel stride = 8 (64B/voxel)
            int base = (((ix << 7) | iy) << 7 | iz) * 8 + sub;
            const uint2* p = gh + base;
#pragma unroll
            for (int c = 0; c < 8; ++c) {
                float w = ((c & 4) ? rx : wx0) *
                          ((c & 2) ? ry : wy0) *
                          ((c & 1) ? rz : wz0);
                uint2 u = __ldg(p + ((c & 4) ? (RESO*RESO*8) : 0)
                                  + ((c & 2) ? (RESO*8)      : 0)
                                  + ((c & 1) ? 8             : 0));
                float2 f01 = __half22float2(*(const __half2*)&u.x);
                float2 f23 = __half22float2(*(const __half2*)&u.y);
                a0 = fmaf(w, f01.x, a0);
                a1 = fmaf(w, f01.y, a1);
                a2 = fmaf(w, f23.x, a2);
                a3 = fmaf(w, f23.y, a3);
            }
        }

        // Per-lane partial dot products
        float pr = a0*brr[0] + a1*brr[1] + a2*brr[2] + a3*brr[3];
        float pg = a0*bgg[0] + a1*bgg[1] + a2*bgg[2] + a3*bgg[3];
        float pb = a0*bbb[0] + a1*bbb[1] + a2*bbb[2] + a3*bbb[3];
        float ps = (sub == 6) ? a3 : 0.f;   // channel 27 = density

        // 8-lane group reduction: two xor rounds (same-parity lanes fully
        // summed), then a merged cross-parity exchange that leaves R/B totals
        // on even lanes and G/sigma totals on odd lanes.
#pragma unroll
        for (int off = 4; off >= 2; off >>= 1) {
            pr += __shfl_xor_sync(FULL, pr, off);
            pg += __shfl_xor_sync(FULL, pg, off);
            pb += __shfl_xor_sync(FULL, pb, off);
            ps += __shfl_xor_sync(FULL, ps, off);
        }
        float r1 = __shfl_xor_sync(FULL, oddl ? pr : pg, 1);
        float r2 = __shfl_xor_sync(FULL, oddl ? pb : ps, 1);
        float vA = (oddl ? pg : pr) + r1;   // even: R total | odd: G total
        float vB = (oddl ? ps : pb) + r2;   // even: B total | odd: sigma total

        // sigma valid on odd lanes
        float sigma = (inb && vB > 1e-10f) ? vB : 0.f;
        float la = -sigma * STEP;
        float la0 = __shfl_sync(FULL, la, 1);
        float la1 = __shfl_sync(FULL, la, 9);
        float la2 = __shfl_sync(FULL, la, 17);
        float la3 = __shfl_sync(FULL, la, 25);

        float la_self = (grp < 2) ? (grp == 0 ? la0 : la1)
                                  : (grp == 2 ? la2 : la3);
        float pre = 0.f;
        if (grp > 0) pre += la0;
        if (grp > 1) pre += la1;
        if (grp > 2) pre += la2;
        float alpha = 1.f - __expf(la_self);
        float w = T * __expf(pre) * alpha;

        float c1 = w * fmaxf(vA + 0.5f, 0.f);
        float c2 = w * fmaxf(vB + 0.5f, 0.f);
        // NOTE: each value is duplicated on 4 lanes per group (same parity);
        // the final full-warp reduction therefore overcounts by exactly 4x,
        // compensated by the 0.25f scale below.
        cr += oddl ? 0.f : c1;
        cg += oddl ? c1  : 0.f;
        cb += oddl ? 0.f : c2;

        T *= __expf(la0 + la1 + la2 + la3);
        // Remaining contribution bounded by T: <=1e-7 abs error. Safe.
        if (T < 1e-8f) break;
    }

    // Full-warp reduction; each channel counted 4x (4 same-parity lanes per
    // group hold identical duplicates) -> exact power-of-two rescale by 0.25.
#pragma unroll
    for (int off = 1; off <= 16; off <<= 1) {
        cr += __shfl_xor_sync(FULL, cr, off);
        cg += __shfl_xor_sync(FULL, cg, off);
        cb += __shfl_xor_sync(FULL, cb, off);
    }

    if (lane == 0) {
        out[gw*3+0] = 0.25f * cr + T;   // + T_final * EMPTY_BRIGHT (=1)
        out[gw*3+1] = 0.25f * cg + T;
        out[gw*3+2] = 0.25f * cb + T;
    }
}

// ---------------------------------------------------------------------------
extern "C" void kernel_launch(void* const* d_in, const int* in_sizes, int n_in,
                              void* d_out, int out_size)
{
    const float* origins = (const float*)d_in[0];   // [NRAYS,3]
    const float* dirs    = (const float*)d_in[1];   // [NRAYS,3]
    const float* density = (const float*)d_in[2];   // [128^3]
    const float* sh      = (const float*)d_in[3];   // [128^3,27]
    float* out = (float*)d_out;                     // [NRAYS,3]

    repack_sh<<<(NVOX * 27 / 4 + 255) / 256, 256>>>(sh);
    repack_density<<<(NVOX + 255) / 256, 256>>>(density);
    render_kernel<<<(NRAYS * 32) / 128, 128>>>(origins, dirs, out);
}

// round 6
// speedup vs baseline: 1.4545x; 1.0106x over previous
#include <cuda_runtime.h>
#include <cuda_fp16.h>

#define RESO    128
#define NRAYS   16384
#define NSAMP   192
#define STEP    0.5f
#define NVOX    (RESO*RESO*RESO)
#define VPB     128     // voxels per repack block

// Padded fp16 SH grid: 32 halves = 64B per voxel (2 voxels per 128B line).
// slots [0..26] = SH channels, [27..31] = zero padding (density stays fp32
// in its original array; lane 7 gathers it directly).
__device__ uint4 g_grid4[NVOX * 4];     // NVOX * 64B

// ---------------------------------------------------------------------------
// Pass 0: repack sh -> fp16 padded layout via smem staging.
// Coalesced float4 reads, fully-coalesced uint4 (16B) writes.
// ---------------------------------------------------------------------------
__global__ void __launch_bounds__(256)
repack_sh(const float* __restrict__ sh)
{
    __shared__ __half sm[VPB * 32];     // 8KB tile
    int tid = threadIdx.x;

    // zero the padding slots [27..31] of each voxel record
    for (int i = tid; i < VPB * 5; i += 256) {
        int v = i / 5, c = 27 + (i - v * 5);
        sm[v * 32 + c] = __ushort_as_half(0);
    }

    // coalesced read + convert: 864 float4 per block
    const float4* src = (const float4*)(sh + (size_t)blockIdx.x * VPB * 27);
    for (int i = tid; i < VPB * 27 / 4; i += 256) {
        float4 f = __ldg(src + i);
        int flat = i * 4;
        int v = flat / 27;
        int c = flat - v * 27;
        float vals[4] = {f.x, f.y, f.z, f.w};
#pragma unroll
        for (int j = 0; j < 4; j++) {
            sm[v * 32 + c] = __float2half(vals[j]);
            if (++c == 27) { c = 0; ++v; }
        }
    }
    __syncthreads();

    // coalesced write-out: 512 uint4 per block (128B per 8 lanes)
    uint4* dst = g_grid4 + (size_t)blockIdx.x * (VPB * 4);
    const uint4* s4 = (const uint4*)sm;
    for (int i = tid; i < VPB * 4; i += 256)
        dst[i] = s4[i];
}

// ---------------------------------------------------------------------------
// Pass 1: render. One warp per ray; 4 samples in flight (8 lanes/sample).
// Lanes 0-6 gather SH quads (LDG.64 fp16); lane 7 gathers fp32 density from
// the original array (L2-resident, 8MB) and accumulates sigma directly.
// ---------------------------------------------------------------------------
__global__ void __launch_bounds__(128)
render_kernel(const float* __restrict__ origins,
              const float* __restrict__ dirs,
              const float* __restrict__ density,
              float* __restrict__ out)
{
    const unsigned FULL = 0xFFFFFFFFu;
    int gw   = (blockIdx.x * blockDim.x + threadIdx.x) >> 5;   // ray id
    int lane = threadIdx.x & 31;
    if (gw >= NRAYS) return;
    int grp = lane >> 3;       // sample-in-flight (0..3)
    int sub = lane & 7;        // channel-quad slot (0..7)
    bool oddl = sub & 1;

    float ox = origins[gw*3+0], oy = origins[gw*3+1], oz = origins[gw*3+2];
    float dx = dirs[gw*3+0],    dy = dirs[gw*3+1],    dz = dirs[gw*3+2];

    // Real SH degree-2 basis (svox2 convention)
    float basis[9];
    basis[0] =  0.28209479177387814f;
    basis[1] = -0.4886025119029199f * dy;
    basis[2] =  0.4886025119029199f * dz;
    basis[3] = -0.4886025119029199f * dx;
    basis[4] =  1.0925484305920792f * dx * dy;
    basis[5] = -1.0925484305920792f * dy * dz;
    basis[6] =  0.31539156525252005f * (2.f*dz*dz - dx*dx - dy*dy);
    basis[7] = -1.0925484305920792f * dx * dz;
    basis[8] =  0.5462742152960396f * (dx*dx - dy*dy);

    // Per-lane channel->color routing premultiplied with basis.
    float brr[4], bgg[4], bbb[4];
#pragma unroll
    for (int m = 0; m < 4; m++) {
        int ch = 4*sub + m;
        float bk = (ch < 27) ? basis[ch % 9] : 0.f;
        brr[m] = (ch < 9)              ? bk : 0.f;
        bgg[m] = (ch >= 9 && ch < 18)  ? bk : 0.f;
        bbb[m] = (ch >= 18 && ch < 27) ? bk : 0.f;
    }

    const uint2* __restrict__ gh = (const uint2*)g_grid4;   // 4 halves per uint2

    float T = 1.f;
    float cr = 0.f, cg = 0.f, cb = 0.f;

    for (int it = 0; it < NSAMP/4; ++it) {
        int   s = it*4 + grp;
        float t = ((float)s + 0.5f) * STEP;
        float px = fmaf(t, dx, ox);
        float py = fmaf(t, dy, oy);
        float pz = fmaf(t, dz, oz);
        bool inb = (px >= 0.f) && (px <= 127.f) &&
                   (py >= 0.f) && (py <= 127.f) &&
                   (pz >= 0.f) && (pz <= 127.f);
        // In-bounds samples form a prefix (convex box): exact early exit.
        if (__ballot_sync(FULL, inb) == 0u) break;

        float fx = floorf(px), fy = floorf(py), fz = floorf(pz);
        float rx = px - fx,    ry = py - fy,    rz = pz - fz;
        int ix = min(max((int)fx, 0), RESO - 2);
        int iy = min(max((int)fy, 0), RESO - 2);
        int iz = min(max((int)fz, 0), RESO - 2);
        float wx0 = 1.f - rx, wy0 = 1.f - ry, wz0 = 1.f - rz;

        int vox = ((ix << 7) | iy) << 7 | iz;
        float a0 = 0.f, a1 = 0.f, a2 = 0.f, a3 = 0.f;
        float ps = 0.f;
        if (inb) {
            if (sub != 7) {
                int base = vox * 8 + sub;           // uint2 units (64B/voxel)
                const uint2* p = gh + base;
#pragma unroll
                for (int c = 0; c < 8; ++c) {
                    float w = ((c & 4) ? rx : wx0) *
                              ((c & 2) ? ry : wy0) *
                              ((c & 1) ? rz : wz0);
                    uint2 u = __ldg(p + ((c & 4) ? (RESO*RESO*8) : 0)
                                      + ((c & 2) ? (RESO*8)      : 0)
                                      + ((c & 1) ? 8             : 0));
                    float2 f01 = __half22float2(*(const __half2*)&u.x);
                    float2 f23 = __half22float2(*(const __half2*)&u.y);
                    a0 = fmaf(w, f01.x, a0);
                    a1 = fmaf(w, f01.y, a1);
                    a2 = fmaf(w, f23.x, a2);
                    a3 = fmaf(w, f23.y, a3);
                }
            } else {
                // lane 7: fp32 density trilerp from the original array
                const float* dp = density + vox;
#pragma unroll
                for (int c = 0; c < 8; ++c) {
                    float w = ((c & 4) ? rx : wx0) *
                              ((c & 2) ? ry : wy0) *
                              ((c & 1) ? rz : wz0);
                    float d = __ldg(dp + ((c & 4) ? (RESO*RESO) : 0)
                                       + ((c & 2) ? RESO        : 0)
                                       + ((c & 1) ? 1           : 0));
                    ps = fmaf(w, d, ps);
                }
            }
        }

        // Per-lane partial dot products
        float pr = a0*brr[0] + a1*brr[1] + a2*brr[2] + a3*brr[3];
        float pg = a0*bgg[0] + a1*bgg[1] + a2*bgg[2] + a3*bgg[3];
        float pb = a0*bbb[0] + a1*bbb[1] + a2*bbb[2] + a3*bbb[3];
        // ps lives on lane 7 (odd parity) -> lands in the sigma slot below.

        // 8-lane group reduction: two xor rounds (same-parity lanes fully
        // summed), then a merged cross-parity exchange that leaves R/B totals
        // on even lanes and G/sigma totals on odd lanes.
#pragma unroll
        for (int off = 4; off >= 2; off >>= 1) {
            pr += __shfl_xor_sync(FULL, pr, off);
            pg += __shfl_xor_sync(FULL, pg, off);
            pb += __shfl_xor_sync(FULL, pb, off);
            ps += __shfl_xor_sync(FULL, ps, off);
        }
        float r1 = __shfl_xor_sync(FULL, oddl ? pr : pg, 1);
        float r2 = __shfl_xor_sync(FULL, oddl ? pb : ps, 1);
        float vA = (oddl ? pg : pr) + r1;   // even: R total | odd: G total
        float vB = (oddl ? ps : pb) + r2;   // even: B total | odd: sigma total

        // sigma valid on odd lanes
        float sigma = (inb && vB > 1e-10f) ? vB : 0.f;
        float la = -sigma * STEP;
        float la0 = __shfl_sync(FULL, la, 1);
        float la1 = __shfl_sync(FULL, la, 9);
        float la2 = __shfl_sync(FULL, la, 17);
        float la3 = __shfl_sync(FULL, la, 25);

        float la_self = (grp < 2) ? (grp == 0 ? la0 : la1)
                                  : (grp == 2 ? la2 : la3);
        float pre = 0.f;
        if (grp > 0) pre += la0;
        if (grp > 1) pre += la1;
        if (grp > 2) pre += la2;
        float alpha = 1.f - __expf(la_self);
        float w = T * __expf(pre) * alpha;

        float c1 = w * fmaxf(vA + 0.5f, 0.f);
        float c2 = w * fmaxf(vB + 0.5f, 0.f);
        // Each value duplicated on 4 same-parity lanes per group; the final
        // full-warp reduction overcounts by exactly 4x -> 0.25f rescale below.
        cr += oddl ? 0.f : c1;
        cg += oddl ? c1  : 0.f;
        cb += oddl ? 0.f : c2;

        T *= __expf(la0 + la1 + la2 + la3);
        // Remaining contribution bounded by T: <=1e-7 abs error. Safe.
        if (T < 1e-8f) break;
    }

    // Full-warp reduction; exact power-of-two rescale for the 4x duplication.
#pragma unroll
    for (int off = 1; off <= 16; off <<= 1) {
        cr += __shfl_xor_sync(FULL, cr, off);
        cg += __shfl_xor_sync(FULL, cg, off);
        cb += __shfl_xor_sync(FULL, cb, off);
    }

    if (lane == 0) {
        out[gw*3+0] = 0.25f * cr + T;   // + T_final * EMPTY_BRIGHT (=1)
        out[gw*3+1] = 0.25f * cg + T;
        out[gw*3+2] = 0.25f * cb + T;
    }
}

// ---------------------------------------------------------------------------
extern "C" void kernel_launch(void* const* d_in, const int* in_sizes, int n_in,
                              void* d_out, int out_size)
{
    const float* origins = (const float*)d_in[0];   // [NRAYS,3]
    const float* dirs    = (const float*)d_in[1];   // [NRAYS,3]
    const float* density = (const float*)d_in[2];   // [128^3]
    const float* sh      = (const float*)d_in[3];   // [128^3,27]
    float* out = (float*)d_out;                     // [NRAYS,3]

    repack_sh<<<NVOX / VPB, 256>>>(sh);
    render_kernel<<<(NRAYS * 32) / 128, 128>>>(origins, dirs, density, out);
}

// round 9
// speedup vs baseline: 1.6682x; 1.1470x over previous
#include <cuda_runtime.h>
#include <cuda_fp16.h>

#define RESO    128
#define NRAYS   16384
#define NSAMP   192
#define STEP    0.5f
#define NVOX    (RESO*RESO*RESO)
#define VPB     128     // voxels per repack block

// Padded fp16 grid: 32 halves = 64B per voxel (2 voxels per 128B line).
// slots [0..26] = SH channels, [27] = density (fp16), [28..31] = zero padding.
__device__ uint4 g_grid4[NVOX * 4];     // NVOX * 64B

// ---------------------------------------------------------------------------
// Pass 0: fused repack (sh + density) -> fp16 padded layout via smem staging.
// Coalesced float4 reads, fully-coalesced uint4 (16B) writes.
// ---------------------------------------------------------------------------
__global__ void __launch_bounds__(256)
repack_grid(const float* __restrict__ sh, const float* __restrict__ density)
{
    __shared__ __half sm[VPB * 32];     // 8KB tile
    int tid = threadIdx.x;

    // zero padding slots [28..31] of each voxel record (slot 27 = density below)
    for (int i = tid; i < VPB * 4; i += 256) {
        int v = i >> 2, c = 28 + (i & 3);
        sm[v * 32 + c] = __ushort_as_half(0);
    }
    // density -> slot 27 (coalesced read, 1 float per voxel)
    if (tid < VPB) {
        float d = __ldg(density + (size_t)blockIdx.x * VPB + tid);
        sm[tid * 32 + 27] = __float2half(d);
    }

    // coalesced read + convert: 864 float4 per block
    const float4* src = (const float4*)(sh + (size_t)blockIdx.x * VPB * 27);
    for (int i = tid; i < VPB * 27 / 4; i += 256) {
        float4 f = __ldg(src + i);
        int flat = i * 4;
        int v = flat / 27;
        int c = flat - v * 27;
        float vals[4] = {f.x, f.y, f.z, f.w};
#pragma unroll
        for (int j = 0; j < 4; j++) {
            sm[v * 32 + c] = __float2half(vals[j]);
            if (++c == 27) { c = 0; ++v; }
        }
    }
    __syncthreads();

    // coalesced write-out: 512 uint4 per block (128B per 8 lanes)
    uint4* dst = g_grid4 + (size_t)blockIdx.x * (VPB * 4);
    const uint4* s4 = (const uint4*)sm;
    for (int i = tid; i < VPB * 4; i += 256)
        dst[i] = s4[i];
}

// ---------------------------------------------------------------------------
// Pass 1: render. One warp per ray; 4 samples in flight (8 lanes/sample);
// lane sub owns channels [4*sub..4*sub+3] as 4 halves (LDG.64). Lane 7
// predicated off (its channels are zero padding) - NO divergent second loop.
// ---------------------------------------------------------------------------
__global__ void __launch_bounds__(128)
render_kernel(const float* __restrict__ origins,
              const float* __restrict__ dirs,
              float* __restrict__ out)
{
    const unsigned FULL = 0xFFFFFFFFu;
    int gw   = (blockIdx.x * blockDim.x + threadIdx.x) >> 5;   // ray id
    int lane = threadIdx.x & 31;
    if (gw >= NRAYS) return;
    int grp = lane >> 3;       // sample-in-flight (0..3)
    int sub = lane & 7;        // channel-quad slot (0..7)
    bool oddl = sub & 1;

    float ox = origins[gw*3+0], oy = origins[gw*3+1], oz = origins[gw*3+2];
    float dx = dirs[gw*3+0],    dy = dirs[gw*3+1],    dz = dirs[gw*3+2];

    // Real SH degree-2 basis (svox2 convention)
    float basis[9];
    basis[0] =  0.28209479177387814f;
    basis[1] = -0.4886025119029199f * dy;
    basis[2] =  0.4886025119029199f * dz;
    basis[3] = -0.4886025119029199f * dx;
    basis[4] =  1.0925484305920792f * dx * dy;
    basis[5] = -1.0925484305920792f * dy * dz;
    basis[6] =  0.31539156525252005f * (2.f*dz*dz - dx*dx - dy*dy);
    basis[7] = -1.0925484305920792f * dx * dz;
    basis[8] =  0.5462742152960396f * (dx*dx - dy*dy);

    // Per-lane channel->color routing premultiplied with basis.
    float brr[4], bgg[4], bbb[4];
#pragma unroll
    for (int m = 0; m < 4; m++) {
        int ch = 4*sub + m;
        float bk = (ch < 27) ? basis[ch % 9] : 0.f;
        brr[m] = (ch < 9)              ? bk : 0.f;
        bgg[m] = (ch >= 9 && ch < 18)  ? bk : 0.f;
        bbb[m] = (ch >= 18 && ch < 27) ? bk : 0.f;
    }

    const uint2* __restrict__ gh = (const uint2*)g_grid4;   // 4 halves per uint2

    float T = 1.f;
    float cr = 0.f, cg = 0.f, cb = 0.f;

    for (int it = 0; it < NSAMP/4; ++it) {
        int   s = it*4 + grp;
        float t = ((float)s + 0.5f) * STEP;
        float px = fmaf(t, dx, ox);
        float py = fmaf(t, dy, oy);
        float pz = fmaf(t, dz, oz);
        bool inb = (px >= 0.f) && (px <= 127.f) &&
                   (py >= 0.f) && (py <= 127.f) &&
                   (pz >= 0.f) && (pz <= 127.f);
        // In-bounds samples form a prefix (convex box): exact early exit.
        if (__ballot_sync(FULL, inb) == 0u) break;

        float fx = floorf(px), fy = floorf(py), fz = floorf(pz);
        float rx = px - fx,    ry = py - fy,    rz = pz - fz;
        int ix = min(max((int)fx, 0), RESO - 2);
        int iy = min(max((int)fy, 0), RESO - 2);
        int iz = min(max((int)fz, 0), RESO - 2);
        float wx0 = 1.f - rx, wy0 = 1.f - ry, wz0 = 1.f - rz;

        float a0 = 0.f, a1 = 0.f, a2 = 0.f, a3 = 0.f;
        if (inb && sub != 7) {
            int base = ((((ix << 7) | iy) << 7) | iz) * 8 + sub;  // uint2 units
            const uint2* p = gh + base;
#pragma unroll
            for (int c = 0; c < 8; ++c) {
                float w = ((c & 4) ? rx : wx0) *
                          ((c & 2) ? ry : wy0) *
                          ((c & 1) ? rz : wz0);
                uint2 u = __ldg(p + ((c & 4) ? (RESO*RESO*8) : 0)
                                  + ((c & 2) ? (RESO*8)      : 0)
                                  + ((c & 1) ? 8             : 0));
                float2 f01 = __half22float2(*(const __half2*)&u.x);
                float2 f23 = __half22float2(*(const __half2*)&u.y);
                a0 = fmaf(w, f01.x, a0);
                a1 = fmaf(w, f01.y, a1);
                a2 = fmaf(w, f23.x, a2);
                a3 = fmaf(w, f23.y, a3);
            }
        }

        // Per-lane partial dot products
        float pr = a0*brr[0] + a1*brr[1] + a2*brr[2] + a3*brr[3];
        float pg = a0*bgg[0] + a1*bgg[1] + a2*bgg[2] + a3*bgg[3];
        float pb = a0*bbb[0] + a1*bbb[1] + a2*bbb[2] + a3*bbb[3];
        float ps = (sub == 6) ? a3 : 0.f;   // channel 27 = density (lane 6 .w)

        // 8-lane group reduction: two xor rounds (same-parity lanes fully
        // summed), then a merged cross-parity exchange that leaves R/B totals
        // on even lanes and G/sigma totals on odd lanes.
#pragma unroll
        for (int off = 4; off >= 2; off >>= 1) {
            pr += __shfl_xor_sync(FULL, pr, off);
            pg += __shfl_xor_sync(FULL, pg, off);
            pb += __shfl_xor_sync(FULL, pb, off);
            ps += __shfl_xor_sync(FULL, ps, off);
        }
        float r1 = __shfl_xor_sync(FULL, oddl ? pr : pg, 1);
        float r2 = __shfl_xor_sync(FULL, oddl ? pb : ps, 1);
        float vA = (oddl ? pg : pr) + r1;   // even: R total | odd: G total
        float vB = (oddl ? ps : pb) + r2;   // even: B total | odd: sigma total

        // sigma valid on odd lanes
        float sigma = (inb && vB > 1e-10f) ? vB : 0.f;
        float la = -sigma * STEP;
        float la0 = __shfl_sync(FULL, la, 1);
        float la1 = __shfl_sync(FULL, la, 9);
        float la2 = __shfl_sync(FULL, la, 17);
        float la3 = __shfl_sync(FULL, la, 25);

        float la_self = (grp < 2) ? (grp == 0 ? la0 : la1)
                                  : (grp == 2 ? la2 : la3);
        float pre = 0.f;
        if (grp > 0) pre += la0;
        if (grp > 1) pre += la1;
        if (grp > 2) pre += la2;
        float alpha = 1.f - __expf(la_self);
        float w = T * __expf(pre) * alpha;

        float c1 = w * fmaxf(vA + 0.5f, 0.f);
        float c2 = w * fmaxf(vB + 0.5f, 0.f);
        // Each value duplicated on 4 same-parity lanes per group; the final
        // full-warp reduction overcounts by exactly 4x -> 0.25f rescale below.
        cr += oddl ? 0.f : c1;
        cg += oddl ? c1  : 0.f;
        cb += oddl ? 0.f : c2;

        T *= __expf(la0 + la1 + la2 + la3);
        // Early exit: leftover contribution bounded by ~2*T on O(1) outputs
        // -> abs error < 2e-5, 50x under the 1e-3 threshold.
        if (T < 1e-5f) break;
    }

    // Full-warp reduction; exact power-of-two rescale for the 4x duplication.
#pragma unroll
    for (int off = 1; off <= 16; off <<= 1) {
        cr += __shfl_xor_sync(FULL, cr, off);
        cg += __shfl_xor_sync(FULL, cg, off);
        cb += __shfl_xor_sync(FULL, cb, off);
    }

    if (lane == 0) {
        out[gw*3+0] = 0.25f * cr + T;   // + T_final * EMPTY_BRIGHT (=1)
        out[gw*3+1] = 0.25f * cg + T;
        out[gw*3+2] = 0.25f * cb + T;
    }
}

// ---------------------------------------------------------------------------
extern "C" void kernel_launch(void* const* d_in, const int* in_sizes, int n_in,
                              void* d_out, int out_size)
{
    const float* origins = (const float*)d_in[0];   // [NRAYS,3]
    const float* dirs    = (const float*)d_in[1];   // [NRAYS,3]
    const float* density = (const float*)d_in[2];   // [128^3]
    const float* sh      = (const float*)d_in[3];   // [128^3,27]
    float* out = (float*)d_out;                     // [NRAYS,3]

    repack_grid<<<NVOX / VPB, 256>>>(sh, density);
    render_kernel<<<(NRAYS * 32) / 128, 128>>>(origins, dirs, out);
}

// round 10
// speedup vs baseline: 1.7029x; 1.0208x over previous
#include <cuda_runtime.h>
#include <cuda_fp16.h>

#define RESO    128
#define NRAYS   16384
#define NSAMP   192
#define STEP    0.5f
#define NVOX    (RESO*RESO*RESO)
#define VPB     128     // voxels per repack block

// Padded fp16 grid: 32 halves = 64B per voxel (2 voxels per 128B line).
// slots [0..26] = SH channels, [27] = density (fp16), [28..31] = zero padding.
__device__ uint4 g_grid4[NVOX * 4];     // NVOX * 64B

// ---------------------------------------------------------------------------
// Pass 0: fused repack (sh + density) -> fp16 padded layout via smem staging.
// Coalesced float4 reads, fully-coalesced uint4 (16B) writes.
// ---------------------------------------------------------------------------
__global__ void __launch_bounds__(256)
repack_grid(const float* __restrict__ sh, const float* __restrict__ density)
{
    __shared__ __half sm[VPB * 32];     // 8KB tile
    int tid = threadIdx.x;

    // zero padding slots [28..31] of each voxel record (slot 27 = density below)
    for (int i = tid; i < VPB * 4; i += 256) {
        int v = i >> 2, c = 28 + (i & 3);
        sm[v * 32 + c] = __ushort_as_half(0);
    }
    // density -> slot 27 (coalesced read, 1 float per voxel)
    if (tid < VPB) {
        float d = __ldg(density + (size_t)blockIdx.x * VPB + tid);
        sm[tid * 32 + 27] = __float2half(d);
    }

    // coalesced read + convert: 864 float4 per block
    const float4* src = (const float4*)(sh + (size_t)blockIdx.x * VPB * 27);
    for (int i = tid; i < VPB * 27 / 4; i += 256) {
        float4 f = __ldg(src + i);
        int flat = i * 4;
        int v = flat / 27;
        int c = flat - v * 27;
        float vals[4] = {f.x, f.y, f.z, f.w};
#pragma unroll
        for (int j = 0; j < 4; j++) {
            sm[v * 32 + c] = __float2half(vals[j]);
            if (++c == 27) { c = 0; ++v; }
        }
    }
    __syncthreads();

    // coalesced write-out: 512 uint4 per block (128B per 8 lanes)
    uint4* dst = g_grid4 + (size_t)blockIdx.x * (VPB * 4);
    const uint4* s4 = (const uint4*)sm;
    for (int i = tid; i < VPB * 4; i += 256)
        dst[i] = s4[i];
}

// ---------------------------------------------------------------------------
// Pass 1: render. One warp per ray; 4 samples in flight (8 lanes/sample);
// lane sub owns channels [4*sub..4*sub+3] as 4 halves (LDG.64). Corner
// accumulation in fp16 (HFMA2). Exit checks deferred to odd iterations
// (an all-out iteration contributes exactly zero, and out-of-bounds is a
// suffix along the ray, so the deferred checks are safe).
// ---------------------------------------------------------------------------
__global__ void __launch_bounds__(128)
render_kernel(const float* __restrict__ origins,
              const float* __restrict__ dirs,
              float* __restrict__ out)
{
    const unsigned FULL = 0xFFFFFFFFu;
    int gw   = (blockIdx.x * blockDim.x + threadIdx.x) >> 5;   // ray id
    int lane = threadIdx.x & 31;
    if (gw >= NRAYS) return;
    int grp = lane >> 3;       // sample-in-flight (0..3)
    int sub = lane & 7;        // channel-quad slot (0..7)
    bool oddl = sub & 1;

    float ox = origins[gw*3+0], oy = origins[gw*3+1], oz = origins[gw*3+2];
    float dx = dirs[gw*3+0],    dy = dirs[gw*3+1],    dz = dirs[gw*3+2];

    // Real SH degree-2 basis (svox2 convention)
    float basis[9];
    basis[0] =  0.28209479177387814f;
    basis[1] = -0.4886025119029199f * dy;
    basis[2] =  0.4886025119029199f * dz;
    basis[3] = -0.4886025119029199f * dx;
    basis[4] =  1.0925484305920792f * dx * dy;
    basis[5] = -1.0925484305920792f * dy * dz;
    basis[6] =  0.31539156525252005f * (2.f*dz*dz - dx*dx - dy*dy);
    basis[7] = -1.0925484305920792f * dx * dz;
    basis[8] =  0.5462742152960396f * (dx*dx - dy*dy);

    // Per-lane channel->color routing premultiplied with basis.
    float brr[4], bgg[4], bbb[4];
#pragma unroll
    for (int m = 0; m < 4; m++) {
        int ch = 4*sub + m;
        float bk = (ch < 27) ? basis[ch % 9] : 0.f;
        brr[m] = (ch < 9)              ? bk : 0.f;
        bgg[m] = (ch >= 9 && ch < 18)  ? bk : 0.f;
        bbb[m] = (ch >= 18 && ch < 27) ? bk : 0.f;
    }

    const uint2* __restrict__ gh = (const uint2*)g_grid4;   // 4 halves per uint2

    float T = 1.f;
    float cr = 0.f, cg = 0.f, cb = 0.f;

#pragma unroll 2
    for (int it = 0; it < NSAMP/4; ++it) {
        int   s = it*4 + grp;
        float t = ((float)s + 0.5f) * STEP;
        float px = fmaf(t, dx, ox);
        float py = fmaf(t, dy, oy);
        float pz = fmaf(t, dz, oz);
        bool inb = (px >= 0.f) && (px <= 127.f) &&
                   (py >= 0.f) && (py <= 127.f) &&
                   (pz >= 0.f) && (pz <= 127.f);

        float fx = floorf(px), fy = floorf(py), fz = floorf(pz);
        float rx = px - fx,    ry = py - fy,    rz = pz - fz;
        int ix = min(max((int)fx, 0), RESO - 2);
        int iy = min(max((int)fy, 0), RESO - 2);
        int iz = min(max((int)fz, 0), RESO - 2);
        float wx0 = 1.f - rx, wy0 = 1.f - ry, wz0 = 1.f - rz;

        __half2 acc01 = __float2half2_rn(0.f);
        __half2 acc23 = __float2half2_rn(0.f);
        if (inb && sub != 7) {
            int base = ((((ix << 7) | iy) << 7) | iz) * 8 + sub;  // uint2 units
            const uint2* p = gh + base;
#pragma unroll
            for (int c = 0; c < 8; ++c) {
                float w = ((c & 4) ? rx : wx0) *
                          ((c & 2) ? ry : wy0) *
                          ((c & 1) ? rz : wz0);
                __half2 wh = __float2half2_rn(w);
                uint2 u = __ldg(p + ((c & 4) ? (RESO*RESO*8) : 0)
                                  + ((c & 2) ? (RESO*8)      : 0)
                                  + ((c & 1) ? 8             : 0));
                acc01 = __hfma2(wh, *(const __half2*)&u.x, acc01);
                acc23 = __hfma2(wh, *(const __half2*)&u.y, acc23);
            }
        }
        float2 f01 = __half22float2(acc01);
        float2 f23 = __half22float2(acc23);

        // Per-lane partial dot products
        float pr = f01.x*brr[0] + f01.y*brr[1] + f23.x*brr[2] + f23.y*brr[3];
        float pg = f01.x*bgg[0] + f01.y*bgg[1] + f23.x*bgg[2] + f23.y*bgg[3];
        float pb = f01.x*bbb[0] + f01.y*bbb[1] + f23.x*bbb[2] + f23.y*bbb[3];
        float ps = (sub == 6) ? f23.y : 0.f;   // channel 27 = density (lane 6 .w)

        // 8-lane group reduction: two xor rounds (same-parity lanes fully
        // summed), then a merged cross-parity exchange that leaves R/B totals
        // on even lanes and G/sigma totals on odd lanes.
#pragma unroll
        for (int off = 4; off >= 2; off >>= 1) {
            pr += __shfl_xor_sync(FULL, pr, off);
            pg += __shfl_xor_sync(FULL, pg, off);
            pb += __shfl_xor_sync(FULL, pb, off);
            ps += __shfl_xor_sync(FULL, ps, off);
        }
        float r1 = __shfl_xor_sync(FULL, oddl ? pr : pg, 1);
        float r2 = __shfl_xor_sync(FULL, oddl ? pb : ps, 1);
        float vA = (oddl ? pg : pr) + r1;   // even: R total | odd: G total
        float vB = (oddl ? ps : pb) + r2;   // even: B total | odd: sigma total

        // sigma valid on odd lanes
        float sigma = (inb && vB > 1e-10f) ? vB : 0.f;
        float la = -sigma * STEP;
        float la0 = __shfl_sync(FULL, la, 1);
        float la1 = __shfl_sync(FULL, la, 9);
        float la2 = __shfl_sync(FULL, la, 17);
        float la3 = __shfl_sync(FULL, la, 25);

        float la_self = (grp < 2) ? (grp == 0 ? la0 : la1)
                                  : (grp == 2 ? la2 : la3);
        float pre = 0.f;
        if (grp > 0) pre += la0;
        if (grp > 1) pre += la1;
        if (grp > 2) pre += la2;
        float alpha = 1.f - __expf(la_self);
        float w = T * __expf(pre) * alpha;

        float c1 = w * fmaxf(vA + 0.5f, 0.f);
        float c2 = w * fmaxf(vB + 0.5f, 0.f);
        // Each value duplicated on 4 same-parity lanes per group; the final
        // full-warp reduction overcounts by exactly 4x -> 0.25f rescale below.
        cr += oddl ? 0.f : c1;
        cg += oddl ? c1  : 0.f;
        cb += oddl ? 0.f : c2;

        T *= __expf(la0 + la1 + la2 + la3);

        // Deferred exits (odd iterations only). Out-of-bounds is a suffix
        // along the ray and an all-out quad contributes exactly zero, so
        // checking only the second quad's ballot is safe. T-cutoff leftover
        // contribution < ~2e-5 abs, 50x under the 1e-3 threshold.
        if (it & 1) {
            unsigned bal = __ballot_sync(FULL, inb);
            if (bal == 0u || T < 1e-5f) break;
        }
    }

    // Full-warp reduction; exact power-of-two rescale for the 4x duplication.
#pragma unroll
    for (int off = 1; off <= 16; off <<= 1) {
        cr += __shfl_xor_sync(FULL, cr, off);
        cg += __shfl_xor_sync(FULL, cg, off);
        cb += __shfl_xor_sync(FULL, cb, off);
    }

    if (lane == 0) {
        out[gw*3+0] = 0.25f * cr + T;   // + T_final * EMPTY_BRIGHT (=1)
        out[gw*3+1] = 0.25f * cg + T;
        out[gw*3+2] = 0.25f * cb + T;
    }
}

// ---------------------------------------------------------------------------
extern "C" void kernel_launch(void* const* d_in, const int* in_sizes, int n_in,
                              void* d_out, int out_size)
{
    const float* origins = (const float*)d_in[0];   // [NRAYS,3]
    const float* dirs    = (const float*)d_in[1];   // [NRAYS,3]
    const float* density = (const float*)d_in[2];   // [128^3]
    const float* sh      = (const float*)d_in[3];   // [128^3,27]
    float* out = (float*)d_out;                     // [NRAYS,3]

    repack_grid<<<NVOX / VPB, 256>>>(sh, density);
    render_kernel<<<(NRAYS * 32) / 128, 128>>>(origins, dirs, out);
}

// round 11
// speedup vs baseline: 1.7325x; 1.0174x over previous
#include <cuda_runtime.h>
#include <cuda_fp16.h>

#define RESO    128
#define NRAYS   16384
#define NSAMP   192
#define STEP    0.5f
#define NVOX    (RESO*RESO*RESO)
#define VPB     128     // voxels per repack block

// Padded fp16 grid: 32 halves = 64B per voxel (2 voxels per 128B line).
// slots [0..26] = SH channels, [27] = density (fp16), [28..31] = zero padding.
__device__ uint4 g_grid4[NVOX * 4];     // NVOX * 64B

// ---------------------------------------------------------------------------
// Pass 0: fused repack (sh + density) -> fp16 padded layout via smem staging.
// Coalesced float4 reads, fully-coalesced uint4 (16B) writes.
// ---------------------------------------------------------------------------
__global__ void __launch_bounds__(256)
repack_grid(const float* __restrict__ sh, const float* __restrict__ density)
{
    __shared__ __half sm[VPB * 32];     // 8KB tile
    int tid = threadIdx.x;

    // zero padding slots [28..31] of each voxel record (slot 27 = density below)
    for (int i = tid; i < VPB * 4; i += 256) {
        int v = i >> 2, c = 28 + (i & 3);
        sm[v * 32 + c] = __ushort_as_half(0);
    }
    // density -> slot 27 (coalesced read, 1 float per voxel)
    if (tid < VPB) {
        float d = __ldg(density + (size_t)blockIdx.x * VPB + tid);
        sm[tid * 32 + 27] = __float2half(d);
    }

    // coalesced read + convert: 864 float4 per block
    const float4* src = (const float4*)(sh + (size_t)blockIdx.x * VPB * 27);
    for (int i = tid; i < VPB * 27 / 4; i += 256) {
        float4 f = __ldg(src + i);
        int flat = i * 4;
        int v = flat / 27;
        int c = flat - v * 27;
        float vals[4] = {f.x, f.y, f.z, f.w};
#pragma unroll
        for (int j = 0; j < 4; j++) {
            sm[v * 32 + c] = __float2half(vals[j]);
            if (++c == 27) { c = 0; ++v; }
        }
    }
    __syncthreads();

    // coalesced write-out: 512 uint4 per block (128B per 8 lanes)
    uint4* dst = g_grid4 + (size_t)blockIdx.x * (VPB * 4);
    const uint4* s4 = (const uint4*)sm;
    for (int i = tid; i < VPB * 4; i += 256)
        dst[i] = s4[i];
}

// ---------------------------------------------------------------------------
// Pass 1: render. One warp per ray; 4 samples in flight (8 lanes/sample);
// lane sub owns channels [4*sub..4*sub+3] as 4 halves (LDG.64). Corner
// accumulation in fp16 (HFMA2). Exit checks deferred to odd iterations.
// 64-thread blocks + minBlocks=20: finer straggler reclamation, 40 warps/SM
// co-residency target (reg cap 51 == current 50-reg codegen, no spills).
// ---------------------------------------------------------------------------
__global__ void __launch_bounds__(64, 20)
render_kernel(const float* __restrict__ origins,
              const float* __restrict__ dirs,
              float* __restrict__ out)
{
    const unsigned FULL = 0xFFFFFFFFu;
    int gw   = (blockIdx.x * blockDim.x + threadIdx.x) >> 5;   // ray id
    int lane = threadIdx.x & 31;
    if (gw >= NRAYS) return;
    int grp = lane >> 3;       // sample-in-flight (0..3)
    int sub = lane & 7;        // channel-quad slot (0..7)
    bool oddl = sub & 1;

    float ox = origins[gw*3+0], oy = origins[gw*3+1], oz = origins[gw*3+2];
    float dx = dirs[gw*3+0],    dy = dirs[gw*3+1],    dz = dirs[gw*3+2];

    // Real SH degree-2 basis (svox2 convention)
    float basis[9];
    basis[0] =  0.28209479177387814f;
    basis[1] = -0.4886025119029199f * dy;
    basis[2] =  0.4886025119029199f * dz;
    basis[3] = -0.4886025119029199f * dx;
    basis[4] =  1.0925484305920792f * dx * dy;
    basis[5] = -1.0925484305920792f * dy * dz;
    basis[6] =  0.31539156525252005f * (2.f*dz*dz - dx*dx - dy*dy);
    basis[7] = -1.0925484305920792f * dx * dz;
    basis[8] =  0.5462742152960396f * (dx*dx - dy*dy);

    // Per-lane channel->color routing premultiplied with basis.
    float brr[4], bgg[4], bbb[4];
#pragma unroll
    for (int m = 0; m < 4; m++) {
        int ch = 4*sub + m;
        float bk = (ch < 27) ? basis[ch % 9] : 0.f;
        brr[m] = (ch < 9)              ? bk : 0.f;
        bgg[m] = (ch >= 9 && ch < 18)  ? bk : 0.f;
        bbb[m] = (ch >= 18 && ch < 27) ? bk : 0.f;
    }

    const uint2* __restrict__ gh = (const uint2*)g_grid4;   // 4 halves per uint2

    float T = 1.f;
    float cr = 0.f, cg = 0.f, cb = 0.f;

#pragma unroll 2
    for (int it = 0; it < NSAMP/4; ++it) {
        int   s = it*4 + grp;
        float t = ((float)s + 0.5f) * STEP;
        float px = fmaf(t, dx, ox);
        float py = fmaf(t, dy, oy);
        float pz = fmaf(t, dz, oz);
        bool inb = (px >= 0.f) && (px <= 127.f) &&
                   (py >= 0.f) && (py <= 127.f) &&
                   (pz >= 0.f) && (pz <= 127.f);

        float fx = floorf(px), fy = floorf(py), fz = floorf(pz);
        float rx = px - fx,    ry = py - fy,    rz = pz - fz;
        int ix = min(max((int)fx, 0), RESO - 2);
        int iy = min(max((int)fy, 0), RESO - 2);
        int iz = min(max((int)fz, 0), RESO - 2);
        float wx0 = 1.f - rx, wy0 = 1.f - ry, wz0 = 1.f - rz;

        __half2 acc01 = __float2half2_rn(0.f);
        __half2 acc23 = __float2half2_rn(0.f);
        if (inb && sub != 7) {
            int base = ((((ix << 7) | iy) << 7) | iz) * 8 + sub;  // uint2 units
            const uint2* p = gh + base;
#pragma unroll
            for (int c = 0; c < 8; ++c) {
                float w = ((c & 4) ? rx : wx0) *
                          ((c & 2) ? ry : wy0) *
                          ((c & 1) ? rz : wz0);
                __half2 wh = __float2half2_rn(w);
                uint2 u = __ldg(p + ((c & 4) ? (RESO*RESO*8) : 0)
                                  + ((c & 2) ? (RESO*8)      : 0)
                                  + ((c & 1) ? 8             : 0));
                acc01 = __hfma2(wh, *(const __half2*)&u.x, acc01);
                acc23 = __hfma2(wh, *(const __half2*)&u.y, acc23);
            }
        }
        float2 f01 = __half22float2(acc01);
        float2 f23 = __half22float2(acc23);

        // Per-lane partial dot products
        float pr = f01.x*brr[0] + f01.y*brr[1] + f23.x*brr[2] + f23.y*brr[3];
        float pg = f01.x*bgg[0] + f01.y*bgg[1] + f23.x*bgg[2] + f23.y*bgg[3];
        float pb = f01.x*bbb[0] + f01.y*bbb[1] + f23.x*bbb[2] + f23.y*bbb[3];
        float ps = (sub == 6) ? f23.y : 0.f;   // channel 27 = density (lane 6 .w)

        // 8-lane group reduction: two xor rounds (same-parity lanes fully
        // summed), then a merged cross-parity exchange that leaves R/B totals
        // on even lanes and G/sigma totals on odd lanes.
#pragma unroll
        for (int off = 4; off >= 2; off >>= 1) {
            pr += __shfl_xor_sync(FULL, pr, off);
            pg += __shfl_xor_sync(FULL, pg, off);
            pb += __shfl_xor_sync(FULL, pb, off);
            ps += __shfl_xor_sync(FULL, ps, off);
        }
        float r1 = __shfl_xor_sync(FULL, oddl ? pr : pg, 1);
        float r2 = __shfl_xor_sync(FULL, oddl ? pb : ps, 1);
        float vA = (oddl ? pg : pr) + r1;   // even: R total | odd: G total
        float vB = (oddl ? ps : pb) + r2;   // even: B total | odd: sigma total

        // sigma valid on odd lanes
        float sigma = (inb && vB > 1e-10f) ? vB : 0.f;
        float la = -sigma * STEP;
        float la0 = __shfl_sync(FULL, la, 1);
        float la1 = __shfl_sync(FULL, la, 9);
        float la2 = __shfl_sync(FULL, la, 17);
        float la3 = __shfl_sync(FULL, la, 25);

        float la_self = (grp < 2) ? (grp == 0 ? la0 : la1)
                                  : (grp == 2 ? la2 : la3);
        float pre = 0.f;
        if (grp > 0) pre += la0;
        if (grp > 1) pre += la1;
        if (grp > 2) pre += la2;
        float alpha = 1.f - __expf(la_self);
        float w = T * __expf(pre) * alpha;

        float c1 = w * fmaxf(vA + 0.5f, 0.f);
        float c2 = w * fmaxf(vB + 0.5f, 0.f);
        // Each value duplicated on 4 same-parity lanes per group; the final
        // full-warp reduction overcounts by exactly 4x -> 0.25f rescale below.
        cr += oddl ? 0.f : c1;
        cg += oddl ? c1  : 0.f;
        cb += oddl ? 0.f : c2;

        T *= __expf(la0 + la1 + la2 + la3);

        // Deferred exits (odd iterations only). Out-of-bounds is a suffix
        // along the ray and an all-out quad contributes exactly zero, so
        // checking only the second quad's ballot is safe. T-cutoff leftover
        // contribution < ~2e-5 abs, 50x under the 1e-3 threshold.
        if (it & 1) {
            unsigned bal = __ballot_sync(FULL, inb);
            if (bal == 0u || T < 1e-5f) break;
        }
    }

    // Full-warp reduction; exact power-of-two rescale for the 4x duplication.
#pragma unroll
    for (int off = 1; off <= 16; off <<= 1) {
        cr += __shfl_xor_sync(FULL, cr, off);
        cg += __shfl_xor_sync(FULL, cg, off);
        cb += __shfl_xor_sync(FULL, cb, off);
    }

    if (lane == 0) {
        out[gw*3+0] = 0.25f * cr + T;   // + T_final * EMPTY_BRIGHT (=1)
        out[gw*3+1] = 0.25f * cg + T;
        out[gw*3+2] = 0.25f * cb + T;
    }
}

// ---------------------------------------------------------------------------
extern "C" void kernel_launch(void* const* d_in, const int* in_sizes, int n_in,
                              void* d_out, int out_size)
{
    const float* origins = (const float*)d_in[0];   // [NRAYS,3]
    const float* dirs    = (const float*)d_in[1];   // [NRAYS,3]
    const float* density = (const float*)d_in[2];   // [128^3]
    const float* sh      = (const float*)d_in[3];   // [128^3,27]
    float* out = (float*)d_out;                     // [NRAYS,3]

    repack_grid<<<NVOX / VPB, 256>>>(sh, density);
    render_kernel<<<(NRAYS * 32) / 64, 64>>>(origins, dirs, out);
}

// round 12
// speedup vs baseline: 2.2047x; 1.2725x over previous
#include <cuda_runtime.h>
#include <cuda_fp16.h>

#define RESO    128
#define NRAYS   16384
#define NSAMP   192
#define STEP    0.5f
#define NVOX    (RESO*RESO*RESO)
#define VPB     128     // voxels per repack block

// Padded fp16 grid: 32 halves = 64B per voxel (4 uint4).
// slots [0..26] = SH channels, [27] = density (fp16), [28..31] = zero padding.
__device__ uint4 g_grid4[NVOX * 4];     // NVOX * 64B

// ---------------------------------------------------------------------------
// Pass 0: fused repack (sh + density) -> fp16 padded layout via smem staging.
// Coalesced float4 reads, fully-coalesced uint4 (16B) writes.
// ---------------------------------------------------------------------------
__global__ void __launch_bounds__(256)
repack_grid(const float* __restrict__ sh, const float* __restrict__ density)
{
    __shared__ __half sm[VPB * 32];     // 8KB tile
    int tid = threadIdx.x;

    // zero padding slots [28..31] of each voxel record (slot 27 = density below)
    for (int i = tid; i < VPB * 4; i += 256) {
        int v = i >> 2, c = 28 + (i & 3);
        sm[v * 32 + c] = __ushort_as_half(0);
    }
    // density -> slot 27 (coalesced read, 1 float per voxel)
    if (tid < VPB) {
        float d = __ldg(density + (size_t)blockIdx.x * VPB + tid);
        sm[tid * 32 + 27] = __float2half(d);
    }

    // coalesced read + convert: 864 float4 per block
    const float4* src = (const float4*)(sh + (size_t)blockIdx.x * VPB * 27);
    for (int i = tid; i < VPB * 27 / 4; i += 256) {
        float4 f = __ldg(src + i);
        int flat = i * 4;
        int v = flat / 27;
        int c = flat - v * 27;
        float vals[4] = {f.x, f.y, f.z, f.w};
#pragma unroll
        for (int j = 0; j < 4; j++) {
            sm[v * 32 + c] = __float2half(vals[j]);
            if (++c == 27) { c = 0; ++v; }
        }
    }
    __syncthreads();

    // coalesced write-out: 512 uint4 per block (128B per 8 lanes)
    uint4* dst = g_grid4 + (size_t)blockIdx.x * (VPB * 4);
    const uint4* s4 = (const uint4*)sm;
    for (int i = tid; i < VPB * 4; i += 256)
        dst[i] = s4[i];
}

// ---------------------------------------------------------------------------
// Pass 1: render. One warp per ray; 8 samples in flight, 4 lanes per sample.
// Lane sub (0..3) loads channels [8sub..8sub+7] via one LDG.128 per corner
// (fp16 HFMA2 accumulation). A 3-shuffle transpose-butterfly leaves lane sub
// owning color sub (R/G/B/sigma) of its sample; a 3-step warp scan over the
// 8 group-representative lanes produces the transmittance prefix.
// ---------------------------------------------------------------------------
__global__ void __launch_bounds__(64, 16)
render_kernel(const float* __restrict__ origins,
              const float* __restrict__ dirs,
              float* __restrict__ out)
{
    const unsigned FULL = 0xFFFFFFFFu;
    int gw   = (blockIdx.x * blockDim.x + threadIdx.x) >> 5;   // ray id
    int lane = threadIdx.x & 31;
    if (gw >= NRAYS) return;
    int grp = lane >> 2;       // sample-in-flight (0..7)
    int sub = lane & 3;        // channel-octet slot / color owner (0..3)

    float ox = origins[gw*3+0], oy = origins[gw*3+1], oz = origins[gw*3+2];
    float dx = dirs[gw*3+0],    dy = dirs[gw*3+1],    dz = dirs[gw*3+2];

    // Real SH degree-2 basis (svox2 convention)
    float basis[9];
    basis[0] =  0.28209479177387814f;
    basis[1] = -0.4886025119029199f * dy;
    basis[2] =  0.4886025119029199f * dz;
    basis[3] = -0.4886025119029199f * dx;
    basis[4] =  1.0925484305920792f * dx * dy;
    basis[5] = -1.0925484305920792f * dy * dz;
    basis[6] =  0.31539156525252005f * (2.f*dz*dz - dx*dx - dy*dy);
    basis[7] = -1.0925484305920792f * dx * dz;
    basis[8] =  0.5462742152960396f * (dx*dx - dy*dy);

    // Two-segment channel routing: lane sub owns channels [8sub..8sub+7],
    // which span at most 2 consecutive colors. colorOf: R<9, G<18, B<27, 27=sigma.
    float cA[8], cB[8];
    {
        int chA = 8*sub;
        int chB = min(8*sub + 7, 27);
        int colA = chA < 9 ? 0 : (chA < 18 ? 1 : (chA < 27 ? 2 : 3));
        int colB = chB < 9 ? 0 : (chB < 18 ? 1 : (chB < 27 ? 2 : 3));
#pragma unroll
        for (int m = 0; m < 8; m++) {
            int ch = 8*sub + m;
            int col = ch < 9 ? 0 : (ch < 18 ? 1 : (ch < 27 ? 2 : (ch == 27 ? 3 : -1)));
            float bk = (ch < 27) ? basis[ch % 9] : (ch == 27 ? 1.f : 0.f);
            cA[m] = (col == colA) ? bk : 0.f;
            cB[m] = (col == colB && colB != colA) ? bk : 0.f;
        }
        // stash colA/colB in predicates below via sub (fixed mapping):
        // sub0: A=R            sub1: A=R, B=G
        // sub2: A=G, B=B       sub3: A=B, B=sigma
    }

    const uint4* __restrict__ gh = g_grid4;   // voxel = 4 uint4

    float T = 1.f;
    float c_acc = 0.f;      // lane sub accumulates color sub (sub3: unused)

    for (int it = 0; it < NSAMP/8; ++it) {
        int   s = it*8 + grp;
        float t = ((float)s + 0.5f) * STEP;
        float px = fmaf(t, dx, ox);
        float py = fmaf(t, dy, oy);
        float pz = fmaf(t, dz, oz);
        bool inb = (px >= 0.f) && (px <= 127.f) &&
                   (py >= 0.f) && (py <= 127.f) &&
                   (pz >= 0.f) && (pz <= 127.f);

        float fx = floorf(px), fy = floorf(py), fz = floorf(pz);
        float rx = px - fx,    ry = py - fy,    rz = pz - fz;
        int ix = min(max((int)fx, 0), RESO - 2);
        int iy = min(max((int)fy, 0), RESO - 2);
        int iz = min(max((int)fz, 0), RESO - 2);
        float wx0 = 1.f - rx, wy0 = 1.f - ry, wz0 = 1.f - rz;

        __half2 acc0 = __float2half2_rn(0.f), acc1 = acc0;
        __half2 acc2 = acc0, acc3 = acc0;
        if (inb) {
            int vox = (((ix << 7) | iy) << 7) | iz;
            const uint4* p = gh + vox * 4 + sub;
#pragma unroll
            for (int c = 0; c < 8; ++c) {
                float w = ((c & 4) ? rx : wx0) *
                          ((c & 2) ? ry : wy0) *
                          ((c & 1) ? rz : wz0);
                __half2 wh = __float2half2_rn(w);
                uint4 u = __ldg(p + ((c & 4) ? (RESO*RESO*4) : 0)
                                  + ((c & 2) ? (RESO*4)      : 0)
                                  + ((c & 1) ? 4             : 0));
                acc0 = __hfma2(wh, *(const __half2*)&u.x, acc0);
                acc1 = __hfma2(wh, *(const __half2*)&u.y, acc1);
                acc2 = __hfma2(wh, *(const __half2*)&u.z, acc2);
                acc3 = __hfma2(wh, *(const __half2*)&u.w, acc3);
            }
        }
        float2 g0 = __half22float2(acc0);
        float2 g1 = __half22float2(acc1);
        float2 g2 = __half22float2(acc2);
        float2 g3 = __half22float2(acc3);
        float f0=g0.x, f1=g0.y, f2=g1.x, f3=g1.y, f4=g2.x, f5=g2.y, f6=g3.x, f7=g3.y;

        float pA = f0*cA[0]+f1*cA[1]+f2*cA[2]+f3*cA[3]+f4*cA[4]+f5*cA[5]+f6*cA[6]+f7*cA[7];
        float pB = f0*cB[0]+f1*cB[1]+f2*cB[2]+f3*cB[3]+f4*cB[4]+f5*cB[5]+f6*cB[6]+f7*cB[7];

        // Map segment partials to per-color contributions v0..v3 (R,G,B,sigma).
        // sub0: pA->R | sub1: pA->R, pB->G | sub2: pA->G, pB->B | sub3: pA->B, pB->sigma
        float v0 = (sub <= 1) ? pA : 0.f;
        float v1 = (sub == 1) ? pB : ((sub == 2) ? pA : 0.f);
        float v2 = (sub == 2) ? pB : ((sub == 3) ? pA : 0.f);
        float v3 = (sub == 3) ? pB : 0.f;

        // Transpose-butterfly over the 4-lane group: lane sub ends with the
        // group total of v_sub. 3 shuffles.
        bool b0 = sub & 1, b1 = sub & 2;
        float sA = __shfl_xor_sync(FULL, b0 ? v0 : v1, 1);
        float A  = (b0 ? v1 : v0) + sA;          // even: sum v0 | odd: sum v1
        float sB = __shfl_xor_sync(FULL, b0 ? v2 : v3, 1);
        float B  = (b0 ? v3 : v2) + sB;          // even: sum v2 | odd: sum v3
        float sF = __shfl_xor_sync(FULL, b1 ? A : B, 2);
        float fin = (b1 ? B : A) + sF;           // lane sub: total of v_sub

        // sigma lives on sub==3 lanes (group-uniform inb).
        float sigma = (inb && fin > 1e-10f) ? fin : 0.f;
        float la = -sigma * STEP;                // valid on rep lanes (sub==3)

        // Inclusive scan of la over the 8 rep lanes (stride-4 aligned).
        float incl = la;
        float u1 = __shfl_up_sync(FULL, incl, 4);  if (lane >= 4)  incl += u1;
        float u2 = __shfl_up_sync(FULL, incl, 8);  if (lane >= 8)  incl += u2;
        float u3 = __shfl_up_sync(FULL, incl, 16); if (lane >= 16) incl += u3;
        float excl = incl - la;

        int rep = lane | 3;
        float pre   = __shfl_sync(FULL, excl, rep);   // prefix for own group
        float lself = __shfl_sync(FULL, la,   rep);   // own group's log-att
        float total = __shfl_sync(FULL, incl, 31);    // sum over all 8

        float e0 = __expf(pre);
        float e1 = __expf(pre + lself);
        float w  = T * (e0 - e1);                 // = T*exp(pre)*(1-exp(la))

        c_acc += (sub == 3) ? 0.f : w * fmaxf(fin + 0.5f, 0.f);
        T *= __expf(total);

        // Exits: all-out iteration contributes exactly 0 and out-of-bounds is
        // a suffix along the ray -> exact break. T-cutoff: leftover < ~2e-5.
        if (__ballot_sync(FULL, inb) == 0u || T < 1e-5f) break;
    }

    // Sum each color across the 8 groups: lanes congruent mod 4 share a color.
    c_acc += __shfl_xor_sync(FULL, c_acc, 4);
    c_acc += __shfl_xor_sync(FULL, c_acc, 8);
    c_acc += __shfl_xor_sync(FULL, c_acc, 16);

    if (lane < 3)
        out[gw*3 + lane] = c_acc + T;   // + T_final * EMPTY_BRIGHT (=1)
}

// ---------------------------------------------------------------------------
extern "C" void kernel_launch(void* const* d_in, const int* in_sizes, int n_in,
                              void* d_out, int out_size)
{
    const float* origins = (const float*)d_in[0];   // [NRAYS,3]
    const float* dirs    = (const float*)d_in[1];   // [NRAYS,3]
    const float* density = (const float*)d_in[2];   // [128^3]
    const float* sh      = (const float*)d_in[3];   // [128^3,27]
    float* out = (float*)d_out;                     // [NRAYS,3]

    repack_grid<<<NVOX / VPB, 256>>>(sh, density);
    render_kernel<<<(NRAYS * 32) / 64, 64>>>(origins, dirs, out);
}